// round 2
// baseline (speedup 1.0000x reference)
#include <cuda_runtime.h>
#include <cuda_bf16.h>
#include <math.h>

// ---------------- problem constants ----------------
#define BB      2
#define LL      2048
#define DMODEL  1024
#define DINNER  2048
#define DTRANK  64
#define DSTATE  16
#define NTOK    (BB*LL)          // 4096
#define VOCAB   32000
#define XDBLW   (DTRANK + 2*DSTATE)   // 96
#define NLAYER  2

// ---------------- scratch (static device globals; no allocs) ----------------
__device__ float g_x   [NTOK * DMODEL];      // activations between layers
__device__ float g_xz  [NTOK * 2 * DINNER];  // in_proj output
__device__ float g_u   [NTOK * DINNER];      // conv+silu output
__device__ float g_xdbl[NTOK * XDBLW];       // x_proj output (dt | B | C)
__device__ float g_del [NTOK * DINNER];      // delta (softplus)
__device__ float g_y   [NTOK * DINNER];      // ssm output (gated)
__device__ float g_xn  [NTOK * DMODEL];      // layernorm output

// ---------------- helpers ----------------
__device__ __forceinline__ float softplusf(float v) {
    return v > 20.f ? v : log1pf(expf(v));
}
__device__ __forceinline__ float siluf(float v) {
    return v / (1.f + __expf(-v));
}

// ---------------- embedding gather ----------------
__global__ void embed_kernel(const int* __restrict__ tokens,
                             const float* __restrict__ emb,
                             float* __restrict__ x)
{
    int t = blockIdx.x;
    int tok = tokens[t];
    const float4* src = (const float4*)(emb + (size_t)tok * DMODEL);
    float4* dst = (float4*)(x + (size_t)t * DMODEL);
    dst[threadIdx.x] = src[threadIdx.x];   // 256 threads * 4 floats = 1024
}

// ---------------- generic NT SGEMM: C[m,n] = sum_k A[m,k]*B[n,k] ----------------
// A: MxK row-major (lda), B: NxK row-major (ldb), C: MxN row-major (ldc).
// M must be a multiple of 128, K a multiple of 16 (true for all calls here).
// N is predicated. EPI==1: C = softplus(acc + bias[n]).
template<int EPI>
__global__ void __launch_bounds__(256) sgemm_nt(
    int M, int N, int K,
    const float* __restrict__ A, int lda,
    const float* __restrict__ B, int ldb,
    float* __restrict__ C, int ldc,
    const float* __restrict__ bias)
{
    constexpr int BM = 128, BN = 128, BK = 16;
    __shared__ float As[BK][BM + 4];
    __shared__ float Bs[BK][BN + 4];

    const int tid  = threadIdx.x;
    const int bm   = blockIdx.y * BM;
    const int bn   = blockIdx.x * BN;
    const int lrow = tid >> 2;           // 0..63
    const int lcol = (tid & 3) << 2;     // 0,4,8,12
    const int tx   = tid & 15;
    const int ty   = tid >> 4;

    float acc[8][8];
#pragma unroll
    for (int i = 0; i < 8; i++)
#pragma unroll
        for (int j = 0; j < 8; j++) acc[i][j] = 0.f;

    for (int k0 = 0; k0 < K; k0 += BK) {
#pragma unroll
        for (int h = 0; h < 2; h++) {
            int r = lrow + h * 64;
            float4 v = *(const float4*)(A + (size_t)(bm + r) * lda + (k0 + lcol));
            As[lcol+0][r] = v.x; As[lcol+1][r] = v.y;
            As[lcol+2][r] = v.z; As[lcol+3][r] = v.w;
        }
#pragma unroll
        for (int h = 0; h < 2; h++) {
            int r = lrow + h * 64;
            float4 v = make_float4(0.f, 0.f, 0.f, 0.f);
            if (bn + r < N)
                v = *(const float4*)(B + (size_t)(bn + r) * ldb + (k0 + lcol));
            Bs[lcol+0][r] = v.x; Bs[lcol+1][r] = v.y;
            Bs[lcol+2][r] = v.z; Bs[lcol+3][r] = v.w;
        }
        __syncthreads();

#pragma unroll
        for (int k = 0; k < BK; k++) {
            float4 a0 = *(const float4*)&As[k][ty * 4];
            float4 a1 = *(const float4*)&As[k][ty * 4 + 64];
            float4 b0 = *(const float4*)&Bs[k][tx * 4];
            float4 b1 = *(const float4*)&Bs[k][tx * 4 + 64];
            float av[8] = {a0.x, a0.y, a0.z, a0.w, a1.x, a1.y, a1.z, a1.w};
            float bv[8] = {b0.x, b0.y, b0.z, b0.w, b1.x, b1.y, b1.z, b1.w};
#pragma unroll
            for (int i = 0; i < 8; i++)
#pragma unroll
                for (int j = 0; j < 8; j++)
                    acc[i][j] = fmaf(av[i], bv[j], acc[i][j]);
        }
        __syncthreads();
    }

    // epilogue: rows always in range (M % 128 == 0, gridDim.y*128 == M)
#pragma unroll
    for (int i = 0; i < 8; i++) {
        int r = bm + ty * 4 + (i < 4 ? i : 64 + (i - 4));
#pragma unroll
        for (int g = 0; g < 2; g++) {
            int c = bn + tx * 4 + g * 64;
            float v[4];
#pragma unroll
            for (int q = 0; q < 4; q++) v[q] = acc[i][g * 4 + q];
            if (EPI == 1) {
#pragma unroll
                for (int q = 0; q < 4; q++)
                    if (c + q < N) v[q] = softplusf(v[q] + __ldg(&bias[c + q]));
            }
            if (c + 3 < N) {
                float4 o = make_float4(v[0], v[1], v[2], v[3]);
                *(float4*)(C + (size_t)r * ldc + c) = o;
            } else {
#pragma unroll
                for (int q = 0; q < 4; q++)
                    if (c + q < N) C[(size_t)r * ldc + c + q] = v[q];
            }
        }
    }
}

// ---------------- causal depthwise conv (K=4) + bias + silu ----------------
// reads u_pre = g_xz[:, 0:DINNER], writes g_u
__global__ void conv_silu_kernel(const float* __restrict__ xz,
                                 const float* __restrict__ cw,   // [DINNER,4]
                                 const float* __restrict__ cb,   // [DINNER]
                                 float* __restrict__ u)
{
    int idx = blockIdx.x * blockDim.x + threadIdx.x;
    if (idx >= NTOK * DINNER) return;
    int e = idx % DINNER;
    int t = idx / DINNER;
    int b = t / LL, l = t % LL;

    float w0 = cw[e*4+0], w1 = cw[e*4+1], w2 = cw[e*4+2], w3 = cw[e*4+3];
    float acc = cb[e];
    const float* base = xz + (size_t)(b * LL) * (2 * DINNER) + e;
    if (l >= 3) acc = fmaf(base[(size_t)(l-3) * (2*DINNER)], w0, acc);
    if (l >= 2) acc = fmaf(base[(size_t)(l-2) * (2*DINNER)], w1, acc);
    if (l >= 1) acc = fmaf(base[(size_t)(l-1) * (2*DINNER)], w2, acc);
    acc = fmaf(base[(size_t)l * (2*DINNER)], w3, acc);
    u[idx] = siluf(acc);
}

// ---------------- selective scan ----------------
// One lane per (b, e, s): 16 lanes per channel, 2 channels per warp.
// y[t,e] = (sum_s h*C + u*D_skip) * silu(z)
__global__ void __launch_bounds__(256) scan_kernel(
    const float* __restrict__ delta,
    const float* __restrict__ u,
    const float* __restrict__ xdbl,
    const float* __restrict__ xz,
    const float* __restrict__ A_log,   // [DINNER*DSTATE] (layer slice)
    const float* __restrict__ D_skip,  // [DINNER]
    float* __restrict__ y)
{
    int warp = (blockIdx.x * blockDim.x + threadIdx.x) >> 5;  // 0..2047
    int lane = threadIdx.x & 31;
    int b = warp / (DINNER / 2);
    int e = (warp % (DINNER / 2)) * 2 + (lane >> 4);
    int s = lane & 15;

    float Ac  = -__expf(A_log[e * DSTATE + s]);
    float dsk = D_skip[e];
    float h = 0.f;
    const size_t tbase = (size_t)b * LL;

    for (int l = 0; l < LL; l++) {
        size_t t = tbase + l;
        float d  = __ldg(&delta[t * DINNER + e]);
        float uu = __ldg(&u    [t * DINNER + e]);
        float Bv = __ldg(&xdbl[t * XDBLW + DTRANK + s]);
        float Cv = __ldg(&xdbl[t * XDBLW + DTRANK + DSTATE + s]);
        h = fmaf(h, __expf(d * Ac), (d * uu) * Bv);
        float part = h * Cv;
        part += __shfl_xor_sync(0xffffffffu, part, 8);
        part += __shfl_xor_sync(0xffffffffu, part, 4);
        part += __shfl_xor_sync(0xffffffffu, part, 2);
        part += __shfl_xor_sync(0xffffffffu, part, 1);
        if (s == 0) {
            float z = xz[t * (2 * DINNER) + DINNER + e];
            y[t * DINNER + e] = (part + uu * dsk) * siluf(z);
        }
    }
}

// ---------------- layernorm over D=1024 ----------------
__global__ void layernorm_kernel(const float* __restrict__ x,
                                 const float* __restrict__ gamma,
                                 const float* __restrict__ beta,
                                 float* __restrict__ out)
{
    __shared__ float red[16];
    __shared__ float sh_mu, sh_rs;
    int t = blockIdx.x;
    const float4* xp = (const float4*)(x + (size_t)t * DMODEL);
    float4 v = xp[threadIdx.x];
    float s  = v.x + v.y + v.z + v.w;
    float s2 = v.x*v.x + v.y*v.y + v.z*v.z + v.w*v.w;
#pragma unroll
    for (int o = 16; o; o >>= 1) {
        s  += __shfl_xor_sync(0xffffffffu, s,  o);
        s2 += __shfl_xor_sync(0xffffffffu, s2, o);
    }
    int wid = threadIdx.x >> 5, lid = threadIdx.x & 31;
    if (lid == 0) { red[wid] = s; red[wid + 8] = s2; }
    __syncthreads();
    if (threadIdx.x == 0) {
        float S = 0.f, S2 = 0.f;
#pragma unroll
        for (int i = 0; i < 8; i++) { S += red[i]; S2 += red[i + 8]; }
        float mu  = S * (1.f / DMODEL);
        float var = S2 * (1.f / DMODEL) - mu * mu;
        sh_mu = mu;
        sh_rs = rsqrtf(var + 1e-5f);
    }
    __syncthreads();
    float mu = sh_mu, rs = sh_rs;
    float4 g  = ((const float4*)gamma)[threadIdx.x];
    float4 bt = ((const float4*)beta )[threadIdx.x];
    float4 o;
    o.x = (v.x - mu) * rs * g.x + bt.x;
    o.y = (v.y - mu) * rs * g.y + bt.y;
    o.z = (v.z - mu) * rs * g.z + bt.z;
    o.w = (v.w - mu) * rs * g.w + bt.w;
    ((float4*)(out + (size_t)t * DMODEL))[threadIdx.x] = o;
}

// ---------------- launch ----------------
extern "C" void kernel_launch(void* const* d_in, const int* in_sizes, int n_in,
                              void* d_out, int out_size)
{
    (void)in_sizes; (void)n_in; (void)out_size;

    const int*   tokens  = (const int*)  d_in[0];
    const float* emb     = (const float*)d_in[1];
    const float* in_w    = (const float*)d_in[2];   // [2, 4096, 1024]
    const float* conv_w  = (const float*)d_in[3];   // [2, 2048, 4]
    const float* conv_b  = (const float*)d_in[4];   // [2, 2048]
    const float* xp_w    = (const float*)d_in[5];   // [2, 96, 2048]
    const float* dt_w    = (const float*)d_in[6];   // [2, 2048, 64]
    const float* dt_b    = (const float*)d_in[7];   // [2, 2048]
    const float* A_log   = (const float*)d_in[8];   // [2, 2048, 16]
    const float* D_skip  = (const float*)d_in[9];   // [2, 2048]
    const float* out_w   = (const float*)d_in[10];  // [2, 1024, 2048]
    const float* gamma   = (const float*)d_in[11];
    const float* beta    = (const float*)d_in[12];
    const float* lm_w    = (const float*)d_in[13];  // [32000, 1024]
    float* logits = (float*)d_out;

    float *x, *xz, *u, *xdbl, *del, *y, *xn;
    cudaGetSymbolAddress((void**)&x,    g_x);
    cudaGetSymbolAddress((void**)&xz,   g_xz);
    cudaGetSymbolAddress((void**)&u,    g_u);
    cudaGetSymbolAddress((void**)&xdbl, g_xdbl);
    cudaGetSymbolAddress((void**)&del,  g_del);
    cudaGetSymbolAddress((void**)&y,    g_y);
    cudaGetSymbolAddress((void**)&xn,   g_xn);

    embed_kernel<<<NTOK, 256>>>(tokens, emb, x);

    for (int layer = 0; layer < NLAYER; layer++) {
        const float* iw  = in_w  + (size_t)layer * 2 * DINNER * DMODEL;
        const float* cw  = conv_w + (size_t)layer * DINNER * 4;
        const float* cb  = conv_b + (size_t)layer * DINNER;
        const float* xw  = xp_w  + (size_t)layer * XDBLW * DINNER;
        const float* dw  = dt_w  + (size_t)layer * DINNER * DTRANK;
        const float* db  = dt_b  + (size_t)layer * DINNER;
        const float* Al  = A_log + (size_t)layer * DINNER * DSTATE;
        const float* Ds  = D_skip + (size_t)layer * DINNER;
        const float* ow  = out_w + (size_t)layer * DMODEL * DINNER;

        // xz = x @ in_w^T   [4096 x 4096]
        sgemm_nt<0><<<dim3(2*DINNER/128, NTOK/128), 256>>>(
            NTOK, 2*DINNER, DMODEL, x, DMODEL, iw, DMODEL, xz, 2*DINNER, nullptr);

        // u = silu(causal_conv(xz[:, :DINNER]))
        conv_silu_kernel<<<(NTOK*DINNER + 255)/256, 256>>>(xz, cw, cb, u);

        // x_dbl = u @ x_proj^T   [4096 x 96]
        sgemm_nt<0><<<dim3(1, NTOK/128), 256>>>(
            NTOK, XDBLW, DINNER, u, DINNER, xw, DINNER, xdbl, XDBLW, nullptr);

        // delta = softplus(dt @ dt_proj^T + dt_b)   [4096 x 2048]
        sgemm_nt<1><<<dim3(DINNER/128, NTOK/128), 256>>>(
            NTOK, DINNER, DTRANK, xdbl, XDBLW, dw, DTRANK, del, DINNER, db);

        // selective scan + D skip + gating -> y
        scan_kernel<<<(BB*DINNER/2)*32/256, 256>>>(del, u, xdbl, xz, Al, Ds, y);

        // x = y @ out_proj^T   [4096 x 1024]
        sgemm_nt<0><<<dim3(DMODEL/128, NTOK/128), 256>>>(
            NTOK, DMODEL, DINNER, y, DINNER, ow, DINNER, x, DMODEL, nullptr);
    }

    layernorm_kernel<<<NTOK, 256>>>(x, gamma, beta, xn);

    // logits = xn @ lm_head^T   [4096 x 32000]
    sgemm_nt<0><<<dim3(VOCAB/128, NTOK/128), 256>>>(
        NTOK, VOCAB, DMODEL, xn, DMODEL, lm_w, DMODEL, logits, VOCAB, nullptr);
}

// round 5
// speedup vs baseline: 1.7719x; 1.7719x over previous
#include <cuda_runtime.h>
#include <cuda_bf16.h>
#include <math.h>
#include <stdint.h>

// ---------------- problem constants ----------------
#define BB      2
#define LL      2048
#define DMODEL  1024
#define DINNER  2048
#define DTRANK  64
#define DSTATE  16
#define NTOK    (BB*LL)          // 4096
#define VOCAB   32000
#define XDBLW   (DTRANK + 2*DSTATE)   // 96
#define NLAYER  2

// ---------------- scratch (static device globals; no allocs) ----------------
__device__ float g_x   [NTOK * DMODEL];
__device__ float g_xz  [NTOK * 2 * DINNER];
__device__ float g_u   [NTOK * DINNER];
__device__ float g_xdbl[NTOK * XDBLW];
__device__ float g_del [NTOK * DINNER];
__device__ float g_y   [NTOK * DINNER];
__device__ float g_xn  [NTOK * DMODEL];

// ---------------- helpers ----------------
__device__ __forceinline__ float softplusf(float v) {
    return v > 20.f ? v : log1pf(expf(v));
}
__device__ __forceinline__ float siluf(float v) {
    return v / (1.f + __expf(-v));
}
__device__ __forceinline__ uint32_t smem_u32(const void* p) {
    uint32_t a;
    asm("{ .reg .u64 t; cvta.to.shared.u64 t, %1; cvt.u32.u64 %0, t; }" : "=r"(a) : "l"(p));
    return a;
}
__device__ __forceinline__ uint32_t f2tf(float f) {
    uint32_t r;
    asm("cvt.rna.tf32.f32 %0, %1;" : "=r"(r) : "f"(f));
    return r;
}
__device__ __forceinline__ void cp16(uint32_t dst, const void* src, uint32_t sz) {
    asm volatile("cp.async.cg.shared.global [%0], [%1], 16, %2;"
                 :: "r"(dst), "l"(src), "r"(sz) : "memory");
}
#define CP_COMMIT() asm volatile("cp.async.commit_group;" ::: "memory")
#define CP_WAIT1()  asm volatile("cp.async.wait_group 1;" ::: "memory")

// ---------------- tf32 mma.sync NT GEMM ----------------
// C[m,n] = sum_k A[m,k]*B[n,k].  CTA tile 128x128, BK=32, 8 warps (2M x 4N),
// warp tile 64x32 via m16n8k8. Triple-buffered cp.async.
// M % 128 == 0, K % 32 == 0, K >= 64. N predicated. EPI==1: softplus(acc+bias[n]).
#define SMLD 36                      // smem row stride in floats (conflict-free)
#define TILE_F (128 * SMLD)          // floats per (A or B) tile
#define STAGE_F (2 * TILE_F)
#define GEMM_SMEM (3 * STAGE_F * 4)  // 110592 bytes

template<int EPI>
__global__ void __launch_bounds__(256) gemm_mma(
    int M, int N, int K,
    const float* __restrict__ A, int lda,
    const float* __restrict__ B, int ldb,
    float* __restrict__ C, int ldc,
    const float* __restrict__ bias)
{
    extern __shared__ float smf[];
    const int tid  = threadIdx.x;
    const int wid  = tid >> 5;
    const int lane = tid & 31;
    const int g    = lane >> 2;      // 0..7
    const int t    = lane & 3;       // 0..3
    const int wm   = wid & 1;        // 2 warps in M
    const int wn   = wid >> 1;       // 4 warps in N
    const int bm   = blockIdx.x * 128;
    const int bn   = blockIdx.y * 128;

    const uint32_t smu = smem_u32(smf);
    float acc[4][4][4];
#pragma unroll
    for (int i = 0; i < 4; i++)
#pragma unroll
        for (int j = 0; j < 4; j++)
#pragma unroll
            for (int q = 0; q < 4; q++) acc[i][j][q] = 0.f;

    const int Kt = K / 32;

    auto load_stage = [&](int st, int kt) {
        const int k0 = kt * 32;
        uint32_t abase = smu + (uint32_t)(st * STAGE_F) * 4u;
        uint32_t bbase = abase + (uint32_t)TILE_F * 4u;
#pragma unroll
        for (int i = 0; i < 4; i++) {
            int idx = tid + i * 256;
            int row = idx >> 3, ch = (idx & 7) << 2;
            const float* ga = A + (size_t)(bm + row) * lda + k0 + ch;
            cp16(abase + (uint32_t)(row * SMLD + ch) * 4u, ga, 16u);
            int brow = bn + row;
            const float* gb = B + (size_t)(brow < N ? brow : 0) * ldb + k0 + ch;
            cp16(bbase + (uint32_t)(row * SMLD + ch) * 4u, gb, brow < N ? 16u : 0u);
        }
    };

    load_stage(0, 0); CP_COMMIT();
    load_stage(1, 1); CP_COMMIT();

    for (int kt = 0; kt < Kt; kt++) {
        CP_WAIT1();
        __syncthreads();
        int nk = kt + 2;
        if (nk < Kt) load_stage(nk % 3, nk);
        CP_COMMIT();

        const float* aS = smf + (kt % 3) * STAGE_F;
        const float* bS = aS + TILE_F;
#pragma unroll
        for (int k = 0; k < 4; k++) {
            const int k0 = k * 8;
            uint32_t af[4][4], bf[4][2];
#pragma unroll
            for (int mt = 0; mt < 4; mt++) {
                int r0 = wm * 64 + mt * 16 + g;
                af[mt][0] = f2tf(aS[r0 * SMLD + k0 + t]);
                af[mt][1] = f2tf(aS[(r0 + 8) * SMLD + k0 + t]);
                af[mt][2] = f2tf(aS[r0 * SMLD + k0 + t + 4]);
                af[mt][3] = f2tf(aS[(r0 + 8) * SMLD + k0 + t + 4]);
            }
#pragma unroll
            for (int nt = 0; nt < 4; nt++) {
                int n0 = wn * 32 + nt * 8 + g;
                bf[nt][0] = f2tf(bS[n0 * SMLD + k0 + t]);
                bf[nt][1] = f2tf(bS[n0 * SMLD + k0 + t + 4]);
            }
#pragma unroll
            for (int mt = 0; mt < 4; mt++)
#pragma unroll
                for (int nt = 0; nt < 4; nt++) {
                    asm volatile(
                        "mma.sync.aligned.m16n8k8.row.col.f32.tf32.tf32.f32 "
                        "{%0,%1,%2,%3}, {%4,%5,%6,%7}, {%8,%9}, {%0,%1,%2,%3};"
                        : "+f"(acc[mt][nt][0]), "+f"(acc[mt][nt][1]),
                          "+f"(acc[mt][nt][2]), "+f"(acc[mt][nt][3])
                        : "r"(af[mt][0]), "r"(af[mt][1]), "r"(af[mt][2]), "r"(af[mt][3]),
                          "r"(bf[nt][0]), "r"(bf[nt][1]));
                }
        }
    }

    // ---- epilogue: direct register -> gmem ----
#pragma unroll
    for (int mt = 0; mt < 4; mt++) {
        int row0 = bm + wm * 64 + mt * 16 + g;
#pragma unroll
        for (int nt = 0; nt < 4; nt++) {
            int col = bn + wn * 32 + nt * 8 + t * 2;
            if (col < N) {
                float v0 = acc[mt][nt][0], v1 = acc[mt][nt][1];
                float v2 = acc[mt][nt][2], v3 = acc[mt][nt][3];
                if (EPI == 1) {
                    float b0 = __ldg(&bias[col]), b1 = __ldg(&bias[col + 1]);
                    v0 = softplusf(v0 + b0); v1 = softplusf(v1 + b1);
                    v2 = softplusf(v2 + b0); v3 = softplusf(v3 + b1);
                }
                *(float2*)(C + (size_t)row0 * ldc + col)       = make_float2(v0, v1);
                *(float2*)(C + (size_t)(row0 + 8) * ldc + col) = make_float2(v2, v3);
            }
        }
    }
}

// ---------------- embedding gather ----------------
__global__ void embed_kernel(const int* __restrict__ tokens,
                             const float* __restrict__ emb,
                             float* __restrict__ x)
{
    int t = blockIdx.x;
    int tok = tokens[t];
    const float4* src = (const float4*)(emb + (size_t)tok * DMODEL);
    float4* dst = (float4*)(x + (size_t)t * DMODEL);
    dst[threadIdx.x] = src[threadIdx.x];
}

// ---------------- causal depthwise conv (K=4) + bias + silu ----------------
__global__ void conv_silu_kernel(const float* __restrict__ xz,
                                 const float* __restrict__ cw,
                                 const float* __restrict__ cb,
                                 float* __restrict__ u)
{
    int idx = blockIdx.x * blockDim.x + threadIdx.x;
    if (idx >= NTOK * DINNER) return;
    int e = idx % DINNER;
    int t = idx / DINNER;
    int b = t / LL, l = t % LL;

    float w0 = cw[e*4+0], w1 = cw[e*4+1], w2 = cw[e*4+2], w3 = cw[e*4+3];
    float acc = cb[e];
    const float* base = xz + (size_t)(b * LL) * (2 * DINNER) + e;
    if (l >= 3) acc = fmaf(base[(size_t)(l-3) * (2*DINNER)], w0, acc);
    if (l >= 2) acc = fmaf(base[(size_t)(l-2) * (2*DINNER)], w1, acc);
    if (l >= 1) acc = fmaf(base[(size_t)(l-1) * (2*DINNER)], w2, acc);
    acc = fmaf(base[(size_t)l * (2*DINNER)], w3, acc);
    u[idx] = siluf(acc);
}

// ---------------- selective scan ----------------
__global__ void __launch_bounds__(256) scan_kernel(
    const float* __restrict__ delta,
    const float* __restrict__ u,
    const float* __restrict__ xdbl,
    const float* __restrict__ xz,
    const float* __restrict__ A_log,
    const float* __restrict__ D_skip,
    float* __restrict__ y)
{
    int warp = (blockIdx.x * blockDim.x + threadIdx.x) >> 5;
    int lane = threadIdx.x & 31;
    int b = warp / (DINNER / 2);
    int e = (warp % (DINNER / 2)) * 2 + (lane >> 4);
    int s = lane & 15;

    float Ac  = -__expf(A_log[e * DSTATE + s]);
    float dsk = D_skip[e];
    float h = 0.f;
    const size_t tbase = (size_t)b * LL;

    for (int l = 0; l < LL; l++) {
        size_t t = tbase + l;
        float d  = __ldg(&delta[t * DINNER + e]);
        float uu = __ldg(&u    [t * DINNER + e]);
        float Bv = __ldg(&xdbl[t * XDBLW + DTRANK + s]);
        float Cv = __ldg(&xdbl[t * XDBLW + DTRANK + DSTATE + s]);
        h = fmaf(h, __expf(d * Ac), (d * uu) * Bv);
        float part = h * Cv;
        part += __shfl_xor_sync(0xffffffffu, part, 8);
        part += __shfl_xor_sync(0xffffffffu, part, 4);
        part += __shfl_xor_sync(0xffffffffu, part, 2);
        part += __shfl_xor_sync(0xffffffffu, part, 1);
        if (s == 0) {
            float z = __ldg(&xz[t * (2 * DINNER) + DINNER + e]);
            y[t * DINNER + e] = (part + uu * dsk) * siluf(z);
        }
    }
}

// ---------------- layernorm ----------------
__global__ void layernorm_kernel(const float* __restrict__ x,
                                 const float* __restrict__ gamma,
                                 const float* __restrict__ beta,
                                 float* __restrict__ out)
{
    __shared__ float red[16];
    __shared__ float sh_mu, sh_rs;
    int t = blockIdx.x;
    const float4* xp = (const float4*)(x + (size_t)t * DMODEL);
    float4 v = xp[threadIdx.x];
    float s  = v.x + v.y + v.z + v.w;
    float s2 = v.x*v.x + v.y*v.y + v.z*v.z + v.w*v.w;
#pragma unroll
    for (int o = 16; o; o >>= 1) {
        s  += __shfl_xor_sync(0xffffffffu, s,  o);
        s2 += __shfl_xor_sync(0xffffffffu, s2, o);
    }
    int wid = threadIdx.x >> 5, lid = threadIdx.x & 31;
    if (lid == 0) { red[wid] = s; red[wid + 8] = s2; }
    __syncthreads();
    if (threadIdx.x == 0) {
        float S = 0.f, S2 = 0.f;
#pragma unroll
        for (int i = 0; i < 8; i++) { S += red[i]; S2 += red[i + 8]; }
        float mu  = S * (1.f / DMODEL);
        float var = S2 * (1.f / DMODEL) - mu * mu;
        sh_mu = mu;
        sh_rs = rsqrtf(var + 1e-5f);
    }
    __syncthreads();
    float mu = sh_mu, rs = sh_rs;
    float4 gm = ((const float4*)gamma)[threadIdx.x];
    float4 bt = ((const float4*)beta )[threadIdx.x];
    float4 o;
    o.x = (v.x - mu) * rs * gm.x + bt.x;
    o.y = (v.y - mu) * rs * gm.y + bt.y;
    o.z = (v.z - mu) * rs * gm.z + bt.z;
    o.w = (v.w - mu) * rs * gm.w + bt.w;
    ((float4*)(out + (size_t)t * DMODEL))[threadIdx.x] = o;
}

// ---------------- launch ----------------
extern "C" void kernel_launch(void* const* d_in, const int* in_sizes, int n_in,
                              void* d_out, int out_size)
{
    (void)in_sizes; (void)n_in; (void)out_size;

    const int*   tokens  = (const int*)  d_in[0];
    const float* emb     = (const float*)d_in[1];
    const float* in_w    = (const float*)d_in[2];
    const float* conv_w  = (const float*)d_in[3];
    const float* conv_b  = (const float*)d_in[4];
    const float* xp_w    = (const float*)d_in[5];
    const float* dt_w    = (const float*)d_in[6];
    const float* dt_b    = (const float*)d_in[7];
    const float* A_log   = (const float*)d_in[8];
    const float* D_skip  = (const float*)d_in[9];
    const float* out_w   = (const float*)d_in[10];
    const float* gamma   = (const float*)d_in[11];
    const float* beta    = (const float*)d_in[12];
    const float* lm_w    = (const float*)d_in[13];
    float* logits = (float*)d_out;

    float *x, *xz, *u, *xdbl, *del, *y, *xn;
    cudaGetSymbolAddress((void**)&x,    g_x);
    cudaGetSymbolAddress((void**)&xz,   g_xz);
    cudaGetSymbolAddress((void**)&u,    g_u);
    cudaGetSymbolAddress((void**)&xdbl, g_xdbl);
    cudaGetSymbolAddress((void**)&del,  g_del);
    cudaGetSymbolAddress((void**)&y,    g_y);
    cudaGetSymbolAddress((void**)&xn,   g_xn);

    cudaFuncSetAttribute(gemm_mma<0>, cudaFuncAttributeMaxDynamicSharedMemorySize, GEMM_SMEM);
    cudaFuncSetAttribute(gemm_mma<1>, cudaFuncAttributeMaxDynamicSharedMemorySize, GEMM_SMEM);

    embed_kernel<<<NTOK, 256>>>(tokens, emb, x);

    for (int layer = 0; layer < NLAYER; layer++) {
        const float* iw = in_w  + (size_t)layer * 2 * DINNER * DMODEL;
        const float* cw = conv_w + (size_t)layer * DINNER * 4;
        const float* cb = conv_b + (size_t)layer * DINNER;
        const float* xw = xp_w  + (size_t)layer * XDBLW * DINNER;
        const float* dw = dt_w  + (size_t)layer * DINNER * DTRANK;
        const float* db = dt_b  + (size_t)layer * DINNER;
        const float* Al = A_log + (size_t)layer * DINNER * DSTATE;
        const float* Ds = D_skip + (size_t)layer * DINNER;
        const float* ow = out_w + (size_t)layer * DMODEL * DINNER;

        // xz = x @ in_w^T   [4096 x 4096], K=1024
        gemm_mma<0><<<dim3(NTOK/128, 2*DINNER/128), 256, GEMM_SMEM>>>(
            NTOK, 2*DINNER, DMODEL, x, DMODEL, iw, DMODEL, xz, 2*DINNER, nullptr);

        conv_silu_kernel<<<(NTOK*DINNER + 255)/256, 256>>>(xz, cw, cb, u);

        // x_dbl = u @ x_proj^T   [4096 x 96], K=2048
        gemm_mma<0><<<dim3(NTOK/128, 1), 256, GEMM_SMEM>>>(
            NTOK, XDBLW, DINNER, u, DINNER, xw, DINNER, xdbl, XDBLW, nullptr);

        // delta = softplus(dt @ dt_proj^T + dt_b)   [4096 x 2048], K=64
        gemm_mma<1><<<dim3(NTOK/128, DINNER/128), 256, GEMM_SMEM>>>(
            NTOK, DINNER, DTRANK, xdbl, XDBLW, dw, DTRANK, del, DINNER, db);

        scan_kernel<<<(BB*DINNER/2)*32/256, 256>>>(del, u, xdbl, xz, Al, Ds, y);

        // x = y @ out_proj^T   [4096 x 1024], K=2048
        gemm_mma<0><<<dim3(NTOK/128, DMODEL/128), 256, GEMM_SMEM>>>(
            NTOK, DMODEL, DINNER, y, DINNER, ow, DINNER, x, DMODEL, nullptr);
    }

    layernorm_kernel<<<NTOK, 256>>>(x, gamma, beta, xn);

    // logits = xn @ lm_head^T   [4096 x 32000], K=1024
    gemm_mma<0><<<dim3(NTOK/128, VOCAB/128), 256, GEMM_SMEM>>>(
        NTOK, VOCAB, DMODEL, xn, DMODEL, lm_w, DMODEL, logits, VOCAB, nullptr);
}